// round 16
// baseline (speedup 1.0000x reference)
#include <cuda_runtime.h>
#include <cuda_bf16.h>
#include <mma.h>
using namespace nvcuda;

// Problem constants (fixed by the reference setup)
#define MAXN 50000
#define MAXE 800000
#define FEAT 128
#define NHEAD 4
#define CDIM 32
#define NGRAPH 64
#define NEG_SLOPE 0.2f
#define SCAN_BS 256

// ---------------- device scratch (no allocations allowed) ----------------
__device__ __align__(256) __nv_bfloat162 g_xpb[MAXN * (FEAT/2)];  // bf16 features for gather
__device__ __align__(256) float g_asrc[MAXN * NHEAD];     // per-node src logits [N,4]
__device__ __align__(256) float g_adst[MAXN * NHEAD];     // per-node dst logits [N,4]
__device__ __align__(256) uint4 g_epack[MAXE];            // {src, ew01 bf16x2, ew23 bf16x2, pad}
__device__ __align__(256) int   g_deg[MAXN];              // in-degree histogram
__device__ __align__(256) int   g_off[MAXN + 1];          // CSR offsets
__device__ __align__(256) int   g_cursor[MAXN];           // CSR fill cursors
__device__ __align__(256) float g_pooled[NGRAPH * FEAT];  // per-graph feature sums
__device__ __align__(256) int   g_bsum[(MAXN + SCAN_BS - 1) / SCAN_BS];  // block sums

// ---------------- K1: xp = x @ W via tf32 tensor cores, fused att dots ----------
// W k-chunks staged through smem (bulk coalesced) so fragment loads hit smem.
// Also zeroes g_deg (runs before hist).
__global__ __launch_bounds__(256) void gemm_att_kernel(
    const float* __restrict__ x, const float* __restrict__ W,
    const float* __restrict__ att_s, const float* __restrict__ att_d, int Nn)
{
    __shared__ __align__(16) float sT[64 * 132];   // 33.8KB: x tile, then output tile
    __shared__ __align__(16) float sW[8 * FEAT];   // 4KB: one W k-chunk (8 rows)
    int tid = threadIdx.x;
    int warp = tid >> 5;
    int row0 = blockIdx.x * 64;

    // zero g_deg (grid covers N: (N+63)/64 blocks x 256 >= N)
    {
        int gid = blockIdx.x * 256 + tid;
        if (gid < Nn) g_deg[gid] = 0;
    }

    for (int idx = tid; idx < 64 * 32; idx += 256) {
        int r = idx >> 5, c4 = idx & 31;
        float4 v = make_float4(0.f, 0.f, 0.f, 0.f);
        if (row0 + r < Nn) v = ((const float4*)(x + (size_t)(row0 + r) * FEAT))[c4];
        ((float4*)(sT + r * 132))[c4] = v;
    }
    __syncthreads();

    int rt = warp >> 2;      // 0..1 : rows rt*32 .. rt*32+31
    int ct = warp & 3;       // 0..3 : cols ct*32 .. ct*32+31

    wmma::fragment<wmma::accumulator, 16, 16, 8, float> acc[2][2];
#pragma unroll
    for (int i = 0; i < 2; i++)
#pragma unroll
        for (int j = 0; j < 2; j++) wmma::fill_fragment(acc[i][j], 0.0f);

    wmma::fragment<wmma::matrix_a, 16, 16, 8, wmma::precision::tf32, wmma::row_major> fa[2];
    wmma::fragment<wmma::matrix_b, 16, 16, 8, wmma::precision::tf32, wmma::row_major> fb[2];

    for (int k0 = 0; k0 < FEAT; k0 += 8) {
        __syncthreads();   // prior consumers done with sW
        // stage W rows [k0, k0+8): 1024 floats = 256 float4, one per thread
        ((float4*)sW)[tid] = ((const float4*)(W + (size_t)k0 * FEAT))[tid];
        __syncthreads();

#pragma unroll
        for (int i = 0; i < 2; i++) {
            wmma::load_matrix_sync(fa[i], sT + (rt * 32 + i * 16) * 132 + k0, 132);
#pragma unroll
            for (int t = 0; t < fa[i].num_elements; t++)
                fa[i].x[t] = wmma::__float_to_tf32(fa[i].x[t]);
        }
#pragma unroll
        for (int j = 0; j < 2; j++) {
            wmma::load_matrix_sync(fb[j], sW + ct * 32 + j * 16, FEAT);
#pragma unroll
            for (int t = 0; t < fb[j].num_elements; t++)
                fb[j].x[t] = wmma::__float_to_tf32(fb[j].x[t]);
        }
#pragma unroll
        for (int i = 0; i < 2; i++)
#pragma unroll
            for (int j = 0; j < 2; j++)
                wmma::mma_sync(acc[i][j], fa[i], fb[j], acc[i][j]);
    }
    __syncthreads();   // all x reads complete before overwriting sT
#pragma unroll
    for (int i = 0; i < 2; i++)
#pragma unroll
        for (int j = 0; j < 2; j++)
            wmma::store_matrix_sync(sT + (rt * 32 + i * 16) * 132 + ct * 32 + j * 16,
                                    acc[i][j], 132, wmma::mem_row_major);
    __syncthreads();

    // bf16 feature write
    for (int idx = tid; idx < 64 * 64; idx += 256) {
        int r = idx >> 6, c2 = idx & 63;
        if (row0 + r < Nn) {
            float lo = sT[r * 132 + c2 * 2];
            float hi = sT[r * 132 + c2 * 2 + 1];
            g_xpb[(size_t)(row0 + r) * (FEAT/2) + c2] = __floats2bfloat162_rn(lo, hi);
        }
    }

    // attention logits in fp32: thread = (row rr, head h)
    {
        int rr = tid >> 2, h = tid & 3;
        if (row0 + rr < Nn) {
            float ds = 0.f, dd = 0.f;
#pragma unroll
            for (int c = 0; c < CDIM; c++) {
                float v = sT[rr * 132 + h * CDIM + c];
                ds += v * att_s[h * CDIM + c];
                dd += v * att_d[h * CDIM + c];
            }
            g_asrc[(row0 + rr) * NHEAD + h] = ds;
            g_adst[(row0 + rr) * NHEAD + h] = dd;
        }
    }
}

// ---------------- K2: in-degree histogram (edge_index is int32) ----------------
__global__ void hist_kernel(const int* __restrict__ ei, int E) {
    int idx = blockIdx.x * blockDim.x + threadIdx.x;
    if (idx < E) atomicAdd(&g_deg[ei[E + idx]], 1);
}

// ---------------- K3a: per-block degree sums (+ zero g_pooled) ----------------
__global__ __launch_bounds__(SCAN_BS) void scan_pass1(int Nn) {
    __shared__ int sh[SCAN_BS];
    int i = blockIdx.x * SCAN_BS + threadIdx.x;
    if (i < NGRAPH * FEAT) g_pooled[i] = 0.f;      // ride-along zero (before agg)
    int v = (i < Nn) ? g_deg[i] : 0;
    sh[threadIdx.x] = v;
    __syncthreads();
    for (int d = SCAN_BS / 2; d > 0; d >>= 1) {
        if (threadIdx.x < d) sh[threadIdx.x] += sh[threadIdx.x + d];
        __syncthreads();
    }
    if (threadIdx.x == 0) g_bsum[blockIdx.x] = sh[0];
}

// ---------------- K3b: per-block scan + offsets + cursors (base computed locally) --
__global__ __launch_bounds__(SCAN_BS) void scan_pass3(int Nn, int nb) {
    __shared__ int sb[SCAN_BS];
    __shared__ int sh[SCAN_BS];
    int t = threadIdx.x;

    sb[t] = (t < nb && t < (int)blockIdx.x) ? g_bsum[t] : 0;
    __syncthreads();
    for (int d = SCAN_BS / 2; d > 0; d >>= 1) {
        if (t < d) sb[t] += sb[t + d];
        __syncthreads();
    }
    int base = sb[0];

    int i = blockIdx.x * SCAN_BS + t;
    int v = (i < Nn) ? g_deg[i] : 0;
    sh[t] = v;
    __syncthreads();
    for (int d = 1; d < SCAN_BS; d <<= 1) {
        int u = (t >= d) ? sh[t - d] : 0;
        __syncthreads();
        sh[t] += u;
        __syncthreads();
    }
    int incl = sh[t];
    int pre = base + incl - v;          // exclusive prefix
    if (i < Nn) {
        g_off[i] = pre;
        g_cursor[i] = pre;
        if (i == Nn - 1) g_off[Nn] = pre + v;
    }
}

// ---------------- K5: CSR fill + packed edge record ----------------
__global__ void csr_kernel(const int* __restrict__ ei, int E) {
    int idx = blockIdx.x * blockDim.x + threadIdx.x;
    if (idx < E) {
        int d = ei[E + idx];
        int s = ei[idx];
        int pos = atomicAdd(&g_cursor[d], 1);
        float4 as = *(const float4*)(g_asrc + s * 4);
        float4 ad = *(const float4*)(g_adst + d * 4);
        float f0 = as.x + ad.x, f1 = as.y + ad.y, f2 = as.z + ad.z, f3 = as.w + ad.w;
        float w0 = __expf(fmaxf(f0, NEG_SLOPE * f0));
        float w1 = __expf(fmaxf(f1, NEG_SLOPE * f1));
        float w2 = __expf(fmaxf(f2, NEG_SLOPE * f2));
        float w3 = __expf(fmaxf(f3, NEG_SLOPE * f3));
        __nv_bfloat162 p01 = __floats2bfloat162_rn(w0, w1);
        __nv_bfloat162 p23 = __floats2bfloat162_rn(w2, w3);
        uint4 r;
        r.x = (unsigned)s;
        r.y = *reinterpret_cast<unsigned*>(&p01);
        r.z = *reinterpret_cast<unsigned*>(&p23);
        r.w = 0;
        g_epack[pos] = r;
    }
}

// ---------------- K6: aggregate + relu + smem-pooled reduction ----------------
// 16 warps/block (512 thr), 2 dst nodes per warp -> 32 nodes/block: halves the
// global flush atomics vs 16-node blocks. Per-warp loop identical to R14.
__global__ __launch_bounds__(512) void agg_kernel(
    const int* __restrict__ batch, const float* __restrict__ bias, int Nn)
{
    __shared__ float spool[2][FEAT];
    int tid = threadIdx.x;
    int wIn = tid >> 5;
    int lane = tid & 31;
    int warp = blockIdx.x * 16 + wIn;
    int i0 = warp * 2;
    int i1 = i0 + 1;
    bool has0 = (i0 < Nn);
    bool has1 = (i1 < Nn);
    int h = lane >> 3;           // head of my 4 columns

    if (tid < 2 * FEAT) ((float*)spool)[tid] = 0.f;

    int nodeBase = blockIdx.x * 32;
    int gFirst = 0, gLast = 0;
    bool anyNode = (nodeBase < Nn);
    if (anyNode) {
        gFirst = batch[nodeBase];
        gLast  = batch[min(nodeBase + 31, Nn - 1)];
    }
    bool smemOK = anyNode && (gLast - gFirst <= 1);
    __syncthreads();

    float4 acc0 = make_float4(0.f, 0.f, 0.f, 0.f);
    float4 acc1 = make_float4(0.f, 0.f, 0.f, 0.f);
    float s0 = 0.f, s1 = 0.f;

    if (has0) {
        float adh = g_adst[i0 * 4 + h];
        float es = g_asrc[i0 * 4 + h] + adh;
        float ws = __expf(fmaxf(es, NEG_SLOPE * es));
        uint2 u = ((const uint2*)(g_xpb + (size_t)i0 * (FEAT/2)))[lane];
        float2 p0 = __bfloat1622float2(*reinterpret_cast<__nv_bfloat162*>(&u.x));
        float2 p1 = __bfloat1622float2(*reinterpret_cast<__nv_bfloat162*>(&u.y));
        acc0 = make_float4(ws * p0.x, ws * p0.y, ws * p1.x, ws * p1.y);
        s0 = ws;
    }
    if (has1) {
        float adh = g_adst[i1 * 4 + h];
        float es = g_asrc[i1 * 4 + h] + adh;
        float ws = __expf(fmaxf(es, NEG_SLOPE * es));
        uint2 u = ((const uint2*)(g_xpb + (size_t)i1 * (FEAT/2)))[lane];
        float2 p0 = __bfloat1622float2(*reinterpret_cast<__nv_bfloat162*>(&u.x));
        float2 p1 = __bfloat1622float2(*reinterpret_cast<__nv_bfloat162*>(&u.y));
        acc1 = make_float4(ws * p0.x, ws * p0.y, ws * p1.x, ws * p1.y);
        s1 = ws;
    }

    int beg0 = has0 ? g_off[i0] : 0, end0 = has0 ? g_off[i0 + 1] : 0;
    int beg1 = has1 ? g_off[i1] : 0, end1 = has1 ? g_off[i1 + 1] : 0;
    int len0 = end0 - beg0, len1 = end1 - beg1;
    int L = max(len0, len1);

#pragma unroll 2
    for (int t = 0; t < L; t++) {
        uint4 pk0 = make_uint4(0, 0, 0, 0);
        uint4 pk1 = make_uint4(0, 0, 0, 0);
        if (t < len0) pk0 = g_epack[beg0 + t];
        if (t < len1) pk1 = g_epack[beg1 + t];
        if (t < len0) {
            unsigned wb = (h < 2) ? pk0.y : pk0.z;
            float2 wp = __bfloat1622float2(*reinterpret_cast<__nv_bfloat162*>(&wb));
            float w = (h & 1) ? wp.y : wp.x;
            s0 += w;
            uint2 u = ((const uint2*)(g_xpb + (size_t)pk0.x * (FEAT/2)))[lane];
            float2 p0 = __bfloat1622float2(*reinterpret_cast<__nv_bfloat162*>(&u.x));
            float2 p1 = __bfloat1622float2(*reinterpret_cast<__nv_bfloat162*>(&u.y));
            acc0.x += w * p0.x; acc0.y += w * p0.y; acc0.z += w * p1.x; acc0.w += w * p1.y;
        }
        if (t < len1) {
            unsigned wb = (h < 2) ? pk1.y : pk1.z;
            float2 wp = __bfloat1622float2(*reinterpret_cast<__nv_bfloat162*>(&wb));
            float w = (h & 1) ? wp.y : wp.x;
            s1 += w;
            uint2 u = ((const uint2*)(g_xpb + (size_t)pk1.x * (FEAT/2)))[lane];
            float2 p0 = __bfloat1622float2(*reinterpret_cast<__nv_bfloat162*>(&u.x));
            float2 p1 = __bfloat1622float2(*reinterpret_cast<__nv_bfloat162*>(&u.y));
            acc1.x += w * p0.x; acc1.y += w * p0.y; acc1.z += w * p1.x; acc1.w += w * p1.y;
        }
    }

    float4 b4 = ((const float4*)bias)[lane];

    if (has0) {
        float inv = 1.0f / s0;
        float o0 = fmaxf(acc0.x * inv + b4.x, 0.f);
        float o1 = fmaxf(acc0.y * inv + b4.y, 0.f);
        float o2 = fmaxf(acc0.z * inv + b4.z, 0.f);
        float o3 = fmaxf(acc0.w * inv + b4.w, 0.f);
        int g = batch[i0];
        if (smemOK) {
            float* sp = spool[g - gFirst] + lane * 4;
            atomicAdd(sp + 0, o0); atomicAdd(sp + 1, o1);
            atomicAdd(sp + 2, o2); atomicAdd(sp + 3, o3);
        } else {
            float* pg = g_pooled + g * FEAT + lane * 4;
            atomicAdd(pg + 0, o0); atomicAdd(pg + 1, o1);
            atomicAdd(pg + 2, o2); atomicAdd(pg + 3, o3);
        }
    }
    if (has1) {
        float inv = 1.0f / s1;
        float o0 = fmaxf(acc1.x * inv + b4.x, 0.f);
        float o1 = fmaxf(acc1.y * inv + b4.y, 0.f);
        float o2 = fmaxf(acc1.z * inv + b4.z, 0.f);
        float o3 = fmaxf(acc1.w * inv + b4.w, 0.f);
        int g = batch[i1];
        if (smemOK) {
            float* sp = spool[g - gFirst] + lane * 4;
            atomicAdd(sp + 0, o0); atomicAdd(sp + 1, o1);
            atomicAdd(sp + 2, o2); atomicAdd(sp + 3, o3);
        } else {
            float* pg = g_pooled + g * FEAT + lane * 4;
            atomicAdd(pg + 0, o0); atomicAdd(pg + 1, o1);
            atomicAdd(pg + 2, o2); atomicAdd(pg + 3, o3);
        }
    }

    __syncthreads();
    if (smemOK && tid < 2 * FEAT) {
        int bank = tid >> 7, c = tid & 127;
        float v = ((float*)spool)[tid];
        int g = gFirst + bank;
        if (v != 0.f && g < NGRAPH)
            atomicAdd(&g_pooled[g * FEAT + c], v);
    }
}

// ---------------- K7: mean + final linear ----------------
__global__ void final_kernel(const int* __restrict__ batch, int Nn,
                             const float* __restrict__ Wl, const float* __restrict__ bl,
                             float* __restrict__ out)
{
    int t = threadIdx.x;
    if (t >= NGRAPH * 2) return;
    int g = t >> 1, o = t & 1;
    int lo = 0, hi = Nn;
    while (lo < hi) { int m = (lo + hi) >> 1; if (batch[m] < g) lo = m + 1; else hi = m; }
    int c0 = lo;
    lo = 0; hi = Nn;
    while (lo < hi) { int m = (lo + hi) >> 1; if (batch[m] < g + 1) lo = m + 1; else hi = m; }
    int cnt = lo - c0;
    float fc = (float)max(cnt, 1);
    float sum = 0.f;
#pragma unroll 4
    for (int k = 0; k < FEAT; k++) sum += g_pooled[g * FEAT + k] * Wl[k * 2 + o];
    out[g * 2 + o] = sum / fc + bl[o];
}

// ---------------- launch ----------------
extern "C" void kernel_launch(void* const* d_in, const int* in_sizes, int n_in,
                              void* d_out, int out_size)
{
    const float* x     = (const float*)d_in[0];
    const int*   ei    = (const int*)d_in[1];     // int32 on the wire
    const int*   batch = (const int*)d_in[2];     // int32 on the wire
    const float* W     = (const float*)d_in[3];
    const float* att_s = (const float*)d_in[4];
    const float* att_d = (const float*)d_in[5];
    const float* bias  = (const float*)d_in[6];
    const float* Wl    = (const float*)d_in[7];
    const float* bl    = (const float*)d_in[8];
    float* out = (float*)d_out;

    int N = in_sizes[0] / FEAT;
    int E = in_sizes[1] / 2;
    int nb = (N + SCAN_BS - 1) / SCAN_BS;

    gemm_att_kernel<<<(N + 63) / 64, 256>>>(x, W, att_s, att_d, N);   // also zeroes g_deg
    hist_kernel<<<(E + 255) / 256, 256>>>(ei, E);
    scan_pass1<<<nb, SCAN_BS>>>(N);                                   // also zeroes g_pooled
    scan_pass3<<<nb, SCAN_BS>>>(N, nb);
    csr_kernel<<<(E + 255) / 256, 256>>>(ei, E);
    {
        int nblocks = (N + 31) / 32;    // 32 nodes per block (16 warps x 2)
        agg_kernel<<<nblocks, 512>>>(batch, bias, N);
    }
    final_kernel<<<1, 128>>>(batch, N, Wl, bl, out);
}

// round 17
// speedup vs baseline: 1.0341x; 1.0341x over previous
#include <cuda_runtime.h>
#include <cuda_bf16.h>
#include <mma.h>
using namespace nvcuda;

// Problem constants (fixed by the reference setup)
#define MAXN 50000
#define MAXE 800000
#define FEAT 128
#define NHEAD 4
#define CDIM 32
#define NGRAPH 64
#define NEG_SLOPE 0.2f
#define SCAN_BS 256
#define READY 0x40000000

// ---------------- device scratch (no allocations allowed) ----------------
__device__ __align__(256) __nv_bfloat162 g_xpb[MAXN * (FEAT/2)];  // bf16 features for gather
__device__ __align__(256) float g_asrc[MAXN * NHEAD];     // per-node src logits [N,4]
__device__ __align__(256) float g_adst[MAXN * NHEAD];     // per-node dst logits [N,4]
__device__ __align__(256) uint4 g_epack[MAXE];            // {src, ew01 bf16x2, ew23 bf16x2, pad}
__device__ __align__(256) int   g_deg[MAXN];              // in-degree histogram
__device__ __align__(256) int   g_off[MAXN + 1];          // CSR offsets
__device__ __align__(256) int   g_cursor[MAXN];           // CSR fill cursors
__device__ __align__(256) float g_pooled[NGRAPH * FEAT];  // per-graph feature sums
__device__ __align__(256) int   g_bsum[(MAXN + SCAN_BS - 1) / SCAN_BS];  // sum|READY per block

// ---------------- K1: xp = x @ W via tf32 tensor cores, fused att dots ----------
// (R14-proven body.) Also zeroes g_deg (runs before hist).
__global__ __launch_bounds__(256) void gemm_att_kernel(
    const float* __restrict__ x, const float* __restrict__ W,
    const float* __restrict__ att_s, const float* __restrict__ att_d, int Nn)
{
    __shared__ __align__(16) float sT[64 * 132];   // 33.8KB: x tile, then output tile
    int tid = threadIdx.x;
    int warp = tid >> 5;
    int row0 = blockIdx.x * 64;

    // zero g_deg (grid covers N: (N+63)/64 blocks x 256 >= N)
    {
        int gid = blockIdx.x * 256 + tid;
        if (gid < Nn) g_deg[gid] = 0;
    }

    for (int idx = tid; idx < 64 * 32; idx += 256) {
        int r = idx >> 5, c4 = idx & 31;
        float4 v = make_float4(0.f, 0.f, 0.f, 0.f);
        if (row0 + r < Nn) v = ((const float4*)(x + (size_t)(row0 + r) * FEAT))[c4];
        ((float4*)(sT + r * 132))[c4] = v;
    }
    __syncthreads();

    int rt = warp >> 2;      // 0..1 : rows rt*32 .. rt*32+31
    int ct = warp & 3;       // 0..3 : cols ct*32 .. ct*32+31

    wmma::fragment<wmma::accumulator, 16, 16, 8, float> acc[2][2];
#pragma unroll
    for (int i = 0; i < 2; i++)
#pragma unroll
        for (int j = 0; j < 2; j++) wmma::fill_fragment(acc[i][j], 0.0f);

    wmma::fragment<wmma::matrix_a, 16, 16, 8, wmma::precision::tf32, wmma::row_major> fa[2];
    wmma::fragment<wmma::matrix_b, 16, 16, 8, wmma::precision::tf32, wmma::row_major> fb[2];

    for (int k0 = 0; k0 < FEAT; k0 += 8) {
#pragma unroll
        for (int i = 0; i < 2; i++) {
            wmma::load_matrix_sync(fa[i], sT + (rt * 32 + i * 16) * 132 + k0, 132);
#pragma unroll
            for (int t = 0; t < fa[i].num_elements; t++)
                fa[i].x[t] = wmma::__float_to_tf32(fa[i].x[t]);
        }
#pragma unroll
        for (int j = 0; j < 2; j++) {
            wmma::load_matrix_sync(fb[j], W + (size_t)k0 * FEAT + ct * 32 + j * 16, FEAT);
#pragma unroll
            for (int t = 0; t < fb[j].num_elements; t++)
                fb[j].x[t] = wmma::__float_to_tf32(fb[j].x[t]);
        }
#pragma unroll
        for (int i = 0; i < 2; i++)
#pragma unroll
            for (int j = 0; j < 2; j++)
                wmma::mma_sync(acc[i][j], fa[i], fb[j], acc[i][j]);
    }
    __syncthreads();   // all x reads complete before overwriting sT
#pragma unroll
    for (int i = 0; i < 2; i++)
#pragma unroll
        for (int j = 0; j < 2; j++)
            wmma::store_matrix_sync(sT + (rt * 32 + i * 16) * 132 + ct * 32 + j * 16,
                                    acc[i][j], 132, wmma::mem_row_major);
    __syncthreads();

    // bf16 feature write
    for (int idx = tid; idx < 64 * 64; idx += 256) {
        int r = idx >> 6, c2 = idx & 63;
        if (row0 + r < Nn) {
            float lo = sT[r * 132 + c2 * 2];
            float hi = sT[r * 132 + c2 * 2 + 1];
            g_xpb[(size_t)(row0 + r) * (FEAT/2) + c2] = __floats2bfloat162_rn(lo, hi);
        }
    }

    // attention logits in fp32: thread = (row rr, head h)
    {
        int rr = tid >> 2, h = tid & 3;
        if (row0 + rr < Nn) {
            float ds = 0.f, dd = 0.f;
#pragma unroll
            for (int c = 0; c < CDIM; c++) {
                float v = sT[rr * 132 + h * CDIM + c];
                ds += v * att_s[h * CDIM + c];
                dd += v * att_d[h * CDIM + c];
            }
            g_asrc[(row0 + rr) * NHEAD + h] = ds;
            g_adst[(row0 + rr) * NHEAD + h] = dd;
        }
    }
}

// ---------------- K2: in-degree histogram, int4-vectorized ----------------
__global__ void hist_kernel(const int* __restrict__ ei, int E) {
    int idx = blockIdx.x * blockDim.x + threadIdx.x;
    int base = idx * 4;
    if (base + 3 < E) {
        int4 d4 = *(const int4*)(ei + E + base);
        atomicAdd(&g_deg[d4.x], 1);
        atomicAdd(&g_deg[d4.y], 1);
        atomicAdd(&g_deg[d4.z], 1);
        atomicAdd(&g_deg[d4.w], 1);
    } else if (base < E) {
        for (int k = base; k < E; k++) atomicAdd(&g_deg[ei[E + k]], 1);
    }
}

// ---------------- K3: fused single-launch scan (parallel lookback) ----------
// Block b publishes its degree-sum as (sum|READY) in g_bsum[b] (data+flag in
// one word, no fence needed), then thread t<b spin-reads predecessor t and a
// block reduce forms the base. All 196 blocks fit in wave 1 -> no deadlock.
// Also zeroes g_pooled (before agg). g_bsum re-zeroed by csr for graph replay.
__global__ __launch_bounds__(SCAN_BS) void scan_fused(int Nn) {
    __shared__ int sh[SCAN_BS];
    __shared__ int sr[SCAN_BS];
    int t = threadIdx.x, b = blockIdx.x;
    int i = b * SCAN_BS + t;
    if (i < NGRAPH * FEAT) g_pooled[i] = 0.f;      // ride-along zero
    int v = (i < Nn) ? g_deg[i] : 0;
    sh[t] = v;
    __syncthreads();
    for (int d = 1; d < SCAN_BS; d <<= 1) {
        int u = (t >= d) ? sh[t - d] : 0;
        __syncthreads();
        sh[t] += u;
        __syncthreads();
    }
    if (t == 0) atomicExch(&g_bsum[b], sh[SCAN_BS - 1] | READY);

    // parallel lookback: thread t waits on predecessor block t
    int pv = 0;
    if (t < b) {
        int val;
        do { val = atomicAdd(&g_bsum[t], 0); } while (!(val & READY));
        pv = val & (READY - 1);
    }
    sr[t] = pv;
    __syncthreads();
    for (int d = SCAN_BS / 2; d > 0; d >>= 1) {
        if (t < d) sr[t] += sr[t + d];
        __syncthreads();
    }
    int base = sr[0];
    int incl = sh[t];
    int pre = base + incl - v;          // exclusive prefix
    if (i < Nn) {
        g_off[i] = pre;
        g_cursor[i] = pre;
        if (i == Nn - 1) g_off[Nn] = pre + v;
    }
}

// ---------------- K5: CSR fill + packed edge record (+ g_bsum reset) --------
__global__ void csr_kernel(const int* __restrict__ ei, int E, int nb) {
    int idx = blockIdx.x * blockDim.x + threadIdx.x;
    if (idx < nb) g_bsum[idx] = 0;      // reset lookback flags for next replay
    if (idx < E) {
        int d = ei[E + idx];
        int s = ei[idx];
        int pos = atomicAdd(&g_cursor[d], 1);
        float4 as = *(const float4*)(g_asrc + s * 4);
        float4 ad = *(const float4*)(g_adst + d * 4);
        float f0 = as.x + ad.x, f1 = as.y + ad.y, f2 = as.z + ad.z, f3 = as.w + ad.w;
        float w0 = __expf(fmaxf(f0, NEG_SLOPE * f0));
        float w1 = __expf(fmaxf(f1, NEG_SLOPE * f1));
        float w2 = __expf(fmaxf(f2, NEG_SLOPE * f2));
        float w3 = __expf(fmaxf(f3, NEG_SLOPE * f3));
        __nv_bfloat162 p01 = __floats2bfloat162_rn(w0, w1);
        __nv_bfloat162 p23 = __floats2bfloat162_rn(w2, w3);
        uint4 r;
        r.x = (unsigned)s;
        r.y = *reinterpret_cast<unsigned*>(&p01);
        r.z = *reinterpret_cast<unsigned*>(&p23);
        r.w = 0;
        g_epack[pos] = r;
    }
}

// ---------------- K6: aggregate + relu + smem-pooled reduction ----------------
// R14-proven: 8 warps/block, 2 dst nodes per warp, lane owns 4 cols, one
// packed 16B load per edge.
__global__ __launch_bounds__(256) void agg_kernel(
    const int* __restrict__ batch, const float* __restrict__ bias, int Nn)
{
    __shared__ float spool[2][FEAT];
    int tid = threadIdx.x;
    int wIn = tid >> 5;
    int lane = tid & 31;
    int warp = blockIdx.x * 8 + wIn;
    int i0 = warp * 2;
    int i1 = i0 + 1;
    bool has0 = (i0 < Nn);
    bool has1 = (i1 < Nn);
    int h = lane >> 3;           // head of my 4 columns

    for (int idx = tid; idx < 2 * FEAT; idx += 256) ((float*)spool)[idx] = 0.f;

    int nodeBase = blockIdx.x * 16;
    int gFirst = 0, gLast = 0;
    bool anyNode = (nodeBase < Nn);
    if (anyNode) {
        gFirst = batch[nodeBase];
        gLast  = batch[min(nodeBase + 15, Nn - 1)];
    }
    bool smemOK = anyNode && (gLast - gFirst <= 1);
    __syncthreads();

    float4 acc0 = make_float4(0.f, 0.f, 0.f, 0.f);
    float4 acc1 = make_float4(0.f, 0.f, 0.f, 0.f);
    float s0 = 0.f, s1 = 0.f;

    if (has0) {
        float adh = g_adst[i0 * 4 + h];
        float es = g_asrc[i0 * 4 + h] + adh;
        float ws = __expf(fmaxf(es, NEG_SLOPE * es));
        uint2 u = ((const uint2*)(g_xpb + (size_t)i0 * (FEAT/2)))[lane];
        float2 p0 = __bfloat1622float2(*reinterpret_cast<__nv_bfloat162*>(&u.x));
        float2 p1 = __bfloat1622float2(*reinterpret_cast<__nv_bfloat162*>(&u.y));
        acc0 = make_float4(ws * p0.x, ws * p0.y, ws * p1.x, ws * p1.y);
        s0 = ws;
    }
    if (has1) {
        float adh = g_adst[i1 * 4 + h];
        float es = g_asrc[i1 * 4 + h] + adh;
        float ws = __expf(fmaxf(es, NEG_SLOPE * es));
        uint2 u = ((const uint2*)(g_xpb + (size_t)i1 * (FEAT/2)))[lane];
        float2 p0 = __bfloat1622float2(*reinterpret_cast<__nv_bfloat162*>(&u.x));
        float2 p1 = __bfloat1622float2(*reinterpret_cast<__nv_bfloat162*>(&u.y));
        acc1 = make_float4(ws * p0.x, ws * p0.y, ws * p1.x, ws * p1.y);
        s1 = ws;
    }

    int beg0 = has0 ? g_off[i0] : 0, end0 = has0 ? g_off[i0 + 1] : 0;
    int beg1 = has1 ? g_off[i1] : 0, end1 = has1 ? g_off[i1 + 1] : 0;
    int len0 = end0 - beg0, len1 = end1 - beg1;
    int L = max(len0, len1);

#pragma unroll 2
    for (int t = 0; t < L; t++) {
        uint4 pk0 = make_uint4(0, 0, 0, 0);
        uint4 pk1 = make_uint4(0, 0, 0, 0);
        if (t < len0) pk0 = g_epack[beg0 + t];
        if (t < len1) pk1 = g_epack[beg1 + t];
        if (t < len0) {
            unsigned wb = (h < 2) ? pk0.y : pk0.z;
            float2 wp = __bfloat1622float2(*reinterpret_cast<__nv_bfloat162*>(&wb));
            float w = (h & 1) ? wp.y : wp.x;
            s0 += w;
            uint2 u = ((const uint2*)(g_xpb + (size_t)pk0.x * (FEAT/2)))[lane];
            float2 p0 = __bfloat1622float2(*reinterpret_cast<__nv_bfloat162*>(&u.x));
            float2 p1 = __bfloat1622float2(*reinterpret_cast<__nv_bfloat162*>(&u.y));
            acc0.x += w * p0.x; acc0.y += w * p0.y; acc0.z += w * p1.x; acc0.w += w * p1.y;
        }
        if (t < len1) {
            unsigned wb = (h < 2) ? pk1.y : pk1.z;
            float2 wp = __bfloat1622float2(*reinterpret_cast<__nv_bfloat162*>(&wb));
            float w = (h & 1) ? wp.y : wp.x;
            s1 += w;
            uint2 u = ((const uint2*)(g_xpb + (size_t)pk1.x * (FEAT/2)))[lane];
            float2 p0 = __bfloat1622float2(*reinterpret_cast<__nv_bfloat162*>(&u.x));
            float2 p1 = __bfloat1622float2(*reinterpret_cast<__nv_bfloat162*>(&u.y));
            acc1.x += w * p0.x; acc1.y += w * p0.y; acc1.z += w * p1.x; acc1.w += w * p1.y;
        }
    }

    float4 b4 = ((const float4*)bias)[lane];

    if (has0) {
        float inv = 1.0f / s0;
        float o0 = fmaxf(acc0.x * inv + b4.x, 0.f);
        float o1 = fmaxf(acc0.y * inv + b4.y, 0.f);
        float o2 = fmaxf(acc0.z * inv + b4.z, 0.f);
        float o3 = fmaxf(acc0.w * inv + b4.w, 0.f);
        int g = batch[i0];
        if (smemOK) {
            float* sp = spool[g - gFirst] + lane * 4;
            atomicAdd(sp + 0, o0); atomicAdd(sp + 1, o1);
            atomicAdd(sp + 2, o2); atomicAdd(sp + 3, o3);
        } else {
            float* pg = g_pooled + g * FEAT + lane * 4;
            atomicAdd(pg + 0, o0); atomicAdd(pg + 1, o1);
            atomicAdd(pg + 2, o2); atomicAdd(pg + 3, o3);
        }
    }
    if (has1) {
        float inv = 1.0f / s1;
        float o0 = fmaxf(acc1.x * inv + b4.x, 0.f);
        float o1 = fmaxf(acc1.y * inv + b4.y, 0.f);
        float o2 = fmaxf(acc1.z * inv + b4.z, 0.f);
        float o3 = fmaxf(acc1.w * inv + b4.w, 0.f);
        int g = batch[i1];
        if (smemOK) {
            float* sp = spool[g - gFirst] + lane * 4;
            atomicAdd(sp + 0, o0); atomicAdd(sp + 1, o1);
            atomicAdd(sp + 2, o2); atomicAdd(sp + 3, o3);
        } else {
            float* pg = g_pooled + g * FEAT + lane * 4;
            atomicAdd(pg + 0, o0); atomicAdd(pg + 1, o1);
            atomicAdd(pg + 2, o2); atomicAdd(pg + 3, o3);
        }
    }

    __syncthreads();
    if (smemOK) {
        for (int idx = tid; idx < 2 * FEAT; idx += 256) {
            int bank = idx >> 7, c = idx & 127;
            float v = ((float*)spool)[idx];
            int g = gFirst + bank;
            if (v != 0.f && g < NGRAPH)
                atomicAdd(&g_pooled[g * FEAT + c], v);
        }
    }
}

// ---------------- K7: mean + final linear ----------------
__global__ void final_kernel(const int* __restrict__ batch, int Nn,
                             const float* __restrict__ Wl, const float* __restrict__ bl,
                             float* __restrict__ out)
{
    int t = threadIdx.x;
    if (t >= NGRAPH * 2) return;
    int g = t >> 1, o = t & 1;
    int lo = 0, hi = Nn;
    while (lo < hi) { int m = (lo + hi) >> 1; if (batch[m] < g) lo = m + 1; else hi = m; }
    int c0 = lo;
    lo = 0; hi = Nn;
    while (lo < hi) { int m = (lo + hi) >> 1; if (batch[m] < g + 1) lo = m + 1; else hi = m; }
    int cnt = lo - c0;
    float fc = (float)max(cnt, 1);
    float sum = 0.f;
#pragma unroll 4
    for (int k = 0; k < FEAT; k++) sum += g_pooled[g * FEAT + k] * Wl[k * 2 + o];
    out[g * 2 + o] = sum / fc + bl[o];
}

// ---------------- launch ----------------
extern "C" void kernel_launch(void* const* d_in, const int* in_sizes, int n_in,
                              void* d_out, int out_size)
{
    const float* x     = (const float*)d_in[0];
    const int*   ei    = (const int*)d_in[1];     // int32 on the wire
    const int*   batch = (const int*)d_in[2];     // int32 on the wire
    const float* W     = (const float*)d_in[3];
    const float* att_s = (const float*)d_in[4];
    const float* att_d = (const float*)d_in[5];
    const float* bias  = (const float*)d_in[6];
    const float* Wl    = (const float*)d_in[7];
    const float* bl    = (const float*)d_in[8];
    float* out = (float*)d_out;

    int N = in_sizes[0] / FEAT;
    int E = in_sizes[1] / 2;
    int nb = (N + SCAN_BS - 1) / SCAN_BS;

    gemm_att_kernel<<<(N + 63) / 64, 256>>>(x, W, att_s, att_d, N);   // also zeroes g_deg
    {
        int nthreads = (E + 3) / 4;
        hist_kernel<<<(nthreads + 255) / 256, 256>>>(ei, E);
    }
    scan_fused<<<nb, SCAN_BS>>>(N);                                   // also zeroes g_pooled
    csr_kernel<<<(E + 255) / 256, 256>>>(ei, E, nb);                  // also resets g_bsum
    {
        int nblocks = (N + 15) / 16;    // 16 nodes per block (8 warps x 2)
        agg_kernel<<<nblocks, 256>>>(batch, bias, N);
    }
    final_kernel<<<1, 128>>>(batch, N, Wl, bl, out);
}